// round 11
// baseline (speedup 1.0000x reference)
#include <cuda_runtime.h>

typedef unsigned long long u64;

#define TOT_REAL 3081u   // 9 fold + 2048 pre + 1024 compute
#define TOT_PAD  3377u   // + 296 no-op items (one per CTA) -> counter self-aligns

// ---------------------------------------------------------------------------
// Scratch (device globals -- no allocation allowed)
// ---------------------------------------------------------------------------
__device__ float g_Wnb[64 * 64];           // W_n @ W_u_bot
__device__ float g_Weu[16 * 64];           // W_e @ W_u_bot
__device__ float g_cu [64];                // b_m @ W_u_bot + b_u
__device__ float g_et2[1024 * 64 * 64];    // folded edge term (16 MB)
__device__ float g_nr [1024 * 64 * 128];   // nodes @ W_r_bot + b_r (32 MB)
__device__ unsigned g_ctr;                 // monotonic work counter (never reset)
__device__ unsigned g_fold;                // +9 per launch
__device__ unsigned g_flag[1024];          // +2 per launch per batch

// ---------------------------------------------------------------------------
// Packed f32x2 helpers (Blackwell FFMA2 -- only reachable via PTX)
// ---------------------------------------------------------------------------
__device__ __forceinline__ u64 pk2(float lo, float hi) {
    u64 r; asm("mov.b64 %0, {%1, %2};" : "=l"(r) : "f"(lo), "f"(hi)); return r;
}
__device__ __forceinline__ void fma2(u64 &d, u64 a, u64 b) {
    asm("fma.rn.f32x2 %0, %1, %2, %0;" : "+l"(d) : "l"(a), "l"(b));
}
__device__ __forceinline__ void add2(u64 &d, u64 a) {
    asm("add.rn.f32x2 %0, %0, %1;" : "+l"(d) : "l"(a));
}
__device__ __forceinline__ void up2(u64 v, float &lo, float &hi) {
    asm("mov.b64 {%0, %1}, %2;" : "=f"(lo), "=f"(hi) : "l"(v));
}

// ---------------------------------------------------------------------------
// One persistent kernel. smem (floats), compute-item layout (as R8):
//   s_hT[0,4352) s_W[4352,12544) s_aT[12544,16896) s_T[16896,20992)
//   s_et[20992,25088) s_mask[25344,25408)
// pre/fold items overlay the same region with their own pointers.
// 25408 floats = 101632 B -> 2 CTAs/SM, grid MUST be 296.
// ---------------------------------------------------------------------------
#define SMEM_BYTES (25408 * 4)

__global__ void __launch_bounds__(256, 2)
k_mpnn(const int* __restrict__ adj, const float* __restrict__ nodes,
       const float* __restrict__ edges,
       const float* __restrict__ W_n, const float* __restrict__ W_e,
       const float* __restrict__ b_m, const float* __restrict__ W_u,
       const float* __restrict__ b_u,
       const float* __restrict__ W_r, const float* __restrict__ b_r,
       float* __restrict__ out)
{
    extern __shared__ float sm[];
    float* s_hT   = sm;
    float* s_W    = sm + 4352;
    float* s_aT   = sm + 12544;
    float* s_T    = sm + 16896;
    float* s_et   = sm + 20992;
    float* s_mask = sm + 25344;
    float* s_red  = s_W;
    __shared__ unsigned s_b;

    int tid = threadIdx.x;
    const int w = tid >> 5, lane = tid & 31;
    const int tx = tid & 15, ty = tid >> 4;     // passes: 4v x 4g
    const int g0 = tx * 4,   v0 = ty * 4;
    const int rx = tid & 31, ry = tid >> 5;     // readout: 8v x 4o
    const int o0 = rx * 4,   v0r = ry * 8;

    while (true) {
        if (tid == 0) s_b = atomicAdd(&g_ctr, 1u);
        __syncthreads();
        unsigned j = s_b;
        unsigned L = j / TOT_PAD;
        unsigned t = j % TOT_PAD;
        if (t >= TOT_REAL) break;   // no-op pad: exactly one per CTA

        if (t < 9u) {
            // ================= FOLD item =================
            float* s_Wu = sm;           // 8192
            float* s_A  = sm + 8192;    // 2048
            int ft = (int)t;
            for (int i = tid; i < 8192; i += 256) s_Wu[i] = W_u[4096 + i];
            if (ft < 8) {
                int r0 = ft * 8;
                for (int i = tid; i < 1024; i += 256) s_A[i] = W_n[r0 * 128 + i];
                __syncthreads();
                int gg = tid & 63, rb = tid >> 6;
                for (int rr = rb; rr < 8; rr += 4) {
                    float acc = 0.f;
                    #pragma unroll 8
                    for (int m = 0; m < 128; m++)
                        acc += s_A[rr * 128 + m] * s_Wu[m * 64 + gg];
                    g_Wnb[(r0 + rr) * 64 + gg] = acc;
                }
            } else {
                for (int i = tid; i < 2048; i += 256) s_A[i] = W_e[i];
                __syncthreads();
                int gg = tid & 63, rb = tid >> 6;
                for (int rr = rb; rr < 16; rr += 4) {
                    float acc = 0.f;
                    #pragma unroll 8
                    for (int m = 0; m < 128; m++)
                        acc += s_A[rr * 128 + m] * s_Wu[m * 64 + gg];
                    g_Weu[rr * 64 + gg] = acc;
                }
                if (tid < 64) {
                    float acc = b_u[tid];
                    #pragma unroll 8
                    for (int m = 0; m < 128; m++)
                        acc += b_m[m] * s_Wu[m * 64 + tid];
                    g_cu[tid] = acc;
                }
            }
            __threadfence();
            __syncthreads();
            if (tid == 0) atomicAdd(&g_fold, 1u);
            continue;
        }

        // decode pre / compute
        int is_pre; unsigned p = 0, b = 0;
        if (t < 265u)       { is_pre = 1; p = t - 9u; }
        else if (t < 2953u) {
            unsigned r = t - 265u, g = r / 3u, m = r % 3u;
            if (m < 2u) { is_pre = 1; p = 256u + 2u * g + m; }
            else        { is_pre = 0; b = g; }
        } else              { is_pre = 0; b = 896u + (t - 2953u); }

        if (is_pre) {
            // ================= PRE item (half-batch) =================
            b = p >> 1;
            int hh = (int)(p & 1u);
            int base_v = (int)b * 64 + hh * 32;
            float* p_Wrb = sm;            // 8192 : W_r rows 64..127
            float* p_nd  = sm + 8192;     // 2048 : 32x64 nodes slice
            float* p_Weu = sm + 10240;    // 1024
            float* p_cu  = sm + 11264;    // 64
            float* p_agg = sm + 11328;    // 512  : 32x16 agg

            for (int i4 = tid; i4 < 2048; i4 += 256)
                *(float4*)&p_Wrb[i4 * 4] = *(const float4*)&W_r[8192 + i4 * 4];
            for (int i4 = tid; i4 < 512; i4 += 256)
                *(float4*)&p_nd[i4 * 4] = *(const float4*)&nodes[base_v * 64 + i4 * 4];

            // edge aggregation: 8 warps x 4 local rows
            const int*   ab = adj   + (long)b * 4096;
            const float* eb = edges + (long)b * 65536;
            for (int tt = 0; tt < 4; tt++) {
                int vl = w * 4 + tt;
                int v  = hh * 32 + vl;
                const int*   arow = ab + v * 64;
                const float* erow = eb + (long)v * 1024;
                float acc[16];
                #pragma unroll
                for (int e = 0; e < 16; e++) acc[e] = 0.f;
                #pragma unroll
                for (int s = 0; s < 2; s++) {
                    int u = lane + s * 32;
                    if (arow[u] != 0) {
                        const float4* e4 = (const float4*)(erow + u * 16);
                        float4 x0 = e4[0], x1 = e4[1], x2 = e4[2], x3 = e4[3];
                        acc[0] += x0.x;  acc[1] += x0.y;  acc[2]  += x0.z;  acc[3]  += x0.w;
                        acc[4] += x1.x;  acc[5] += x1.y;  acc[6]  += x1.z;  acc[7]  += x1.w;
                        acc[8] += x2.x;  acc[9] += x2.y;  acc[10] += x2.z;  acc[11] += x2.w;
                        acc[12]+= x3.x;  acc[13]+= x3.y;  acc[14] += x3.z;  acc[15] += x3.w;
                    }
                }
                #pragma unroll
                for (int off = 16; off > 0; off >>= 1) {
                    #pragma unroll
                    for (int e = 0; e < 16; e++)
                        acc[e] += __shfl_xor_sync(0xffffffffu, acc[e], off);
                }
                if (lane == 0) {
                    float4* dst = (float4*)&p_agg[vl * 16];
                    dst[0] = make_float4(acc[0],  acc[1],  acc[2],  acc[3]);
                    dst[1] = make_float4(acc[4],  acc[5],  acc[6],  acc[7]);
                    dst[2] = make_float4(acc[8],  acc[9],  acc[10], acc[11]);
                    dst[3] = make_float4(acc[12], acc[13], acc[14], acc[15]);
                }
            }
            if (tid == 0) {   // fold outputs needed below
                unsigned tgt = 9u * (L + 1u);
                while (atomicAdd(&g_fold, 0u) < tgt) __nanosleep(64);
                __threadfence();
            }
            __syncthreads();
            for (int i = tid; i < 1024; i += 256) p_Weu[i] = __ldcg(&g_Weu[i]);
            if (tid < 64) p_cu[tid] = __ldcg(&g_cu[tid]);
            __syncthreads();

            // et2 tile: 32 rows x 64 cols -> g_et2
            {
                int r = tid >> 3, q0 = (tid & 7) * 8;
                float4 c0 = *(const float4*)&p_cu[q0];
                float4 c1 = *(const float4*)&p_cu[q0 + 4];
                float e0 = c0.x, e1 = c0.y, e2 = c0.z, e3 = c0.w;
                float e4 = c1.x, e5 = c1.y, e6 = c1.z, e7 = c1.w;
                #pragma unroll
                for (int e = 0; e < 16; e++) {
                    float a = p_agg[r * 16 + e];
                    float4 u0 = *(const float4*)&p_Weu[e * 64 + q0];
                    float4 u1 = *(const float4*)&p_Weu[e * 64 + q0 + 4];
                    e0 += a * u0.x; e1 += a * u0.y; e2 += a * u0.z; e3 += a * u0.w;
                    e4 += a * u1.x; e5 += a * u1.y; e6 += a * u1.z; e7 += a * u1.w;
                }
                float* dst = &g_et2[(long)(base_v + r) * 64 + q0];
                *(float4*)&dst[0] = make_float4(e0, e1, e2, e3);
                *(float4*)&dst[4] = make_float4(e4, e5, e6, e7);
            }
            // nr tile: 32 rows x 128 cols -> g_nr   (f32x2)
            {
                int r = tid >> 3, q0 = (tid & 7) * 16;
                u64 acc[8];
                {
                    float4 b0 = *(const float4*)&b_r[q0];
                    float4 b1 = *(const float4*)&b_r[q0 + 4];
                    float4 b2 = *(const float4*)&b_r[q0 + 8];
                    float4 b3 = *(const float4*)&b_r[q0 + 12];
                    acc[0] = pk2(b0.x, b0.y); acc[1] = pk2(b0.z, b0.w);
                    acc[2] = pk2(b1.x, b1.y); acc[3] = pk2(b1.z, b1.w);
                    acc[4] = pk2(b2.x, b2.y); acc[5] = pk2(b2.z, b2.w);
                    acc[6] = pk2(b3.x, b3.y); acc[7] = pk2(b3.z, b3.w);
                }
                #pragma unroll 4
                for (int k = 0; k < 64; k++) {
                    float nk = p_nd[r * 64 + k];
                    u64 np = pk2(nk, nk);
                    ulonglong2 q0v = *(const ulonglong2*)&p_Wrb[k * 128 + q0];
                    ulonglong2 q1v = *(const ulonglong2*)&p_Wrb[k * 128 + q0 + 4];
                    ulonglong2 q2v = *(const ulonglong2*)&p_Wrb[k * 128 + q0 + 8];
                    ulonglong2 q3v = *(const ulonglong2*)&p_Wrb[k * 128 + q0 + 12];
                    fma2(acc[0], np, q0v.x); fma2(acc[1], np, q0v.y);
                    fma2(acc[2], np, q1v.x); fma2(acc[3], np, q1v.y);
                    fma2(acc[4], np, q2v.x); fma2(acc[5], np, q2v.y);
                    fma2(acc[6], np, q3v.x); fma2(acc[7], np, q3v.y);
                }
                float* dst = &g_nr[(long)(base_v + r) * 128 + q0];
                ulonglong2 o;
                o.x = acc[0]; o.y = acc[1]; *(ulonglong2*)&dst[0]  = o;
                o.x = acc[2]; o.y = acc[3]; *(ulonglong2*)&dst[4]  = o;
                o.x = acc[4]; o.y = acc[5]; *(ulonglong2*)&dst[8]  = o;
                o.x = acc[6]; o.y = acc[7]; *(ulonglong2*)&dst[12] = o;
            }
            __threadfence();
            __syncthreads();
            if (tid == 0) atomicAdd(&g_flag[b], 1u);
            continue;
        }

        // ================= COMPUTE item (one batch) =================
        const float* nb = nodes + b * 4096;
        const int*   ab = adj   + b * 4096;
        // Stage ONLY pure inputs before the wait.
        for (int i4 = tid; i4 < 1024; i4 += 256) {
            int v = i4 >> 4, f = (i4 & 15) * 4;
            float4 hv = *(const float4*)&nb[v * 64 + f];
            s_hT[(f + 0) * 68 + v] = hv.x;
            s_hT[(f + 1) * 68 + v] = hv.y;
            s_hT[(f + 2) * 68 + v] = hv.z;
            s_hT[(f + 3) * 68 + v] = hv.w;
            int4 a4 = *(const int4*)&ab[v * 64 + f];
            s_aT[(f + 0) * 68 + v] = (float)a4.x;
            s_aT[(f + 1) * 68 + v] = (float)a4.y;
            s_aT[(f + 2) * 68 + v] = (float)a4.z;
            s_aT[(f + 3) * 68 + v] = (float)a4.w;
        }
        // WAIT for this batch's pre items (implies folds complete too) BEFORE
        // touching g_Wnb / g_et2.  (R9 bug: g_Wnb was read before this wait.)
        if (tid == 0) {
            unsigned tgt = 2u * (L + 1u);
            while (atomicAdd(&g_flag[b], 0u) < tgt) __nanosleep(64);
            __threadfence();
        }
        __syncthreads();
        for (int i4 = tid; i4 < 2048; i4 += 256) {
            int f = i4 >> 5, gq = (i4 & 31) * 4;
            *(float4*)&s_W[f * 128 + gq] = (gq < 64)
                ? *(const float4*)&W_u[f * 64 + gq]
                : __ldcg((const float4*)&g_Wnb[f * 64 + gq - 64]);
        }
        for (int i4 = tid; i4 < 1024; i4 += 256)
            *(float4*)&s_et[i4 * 4] = __ldcg((const float4*)&g_et2[(long)b * 4096 + i4 * 4]);
        if (tid < 64) {
            float s = 0.f;
            #pragma unroll 8
            for (int u = 0; u < 64; u++) s += s_aT[u * 68 + tid];
            s_mask[tid] = (s > 0.f) ? 1.f : 0.f;
        }
        __syncthreads();
        float mk[4];
        #pragma unroll
        for (int i = 0; i < 4; i++) mk[i] = s_mask[v0 + i];

        // ---- 4 message passes (proven R7/R8 core) ----
        for (int pass = 0; pass < 4; pass++) {
            u64 G[4][2], T[4][2];
            #pragma unroll
            for (int i = 0; i < 4; i++) {
                G[i][0] = 0ull; G[i][1] = 0ull;
                T[i][0] = 0ull; T[i][1] = 0ull;
            }
            #pragma unroll 4
            for (int f = 0; f < 64; f++) {
                ulonglong2 wg = *(const ulonglong2*)&s_W[f * 128 + g0];
                ulonglong2 wt = *(const ulonglong2*)&s_W[f * 128 + 64 + g0];
                float4 hv = *(const float4*)&s_hT[f * 68 + v0];
                u64 hp;
                hp = pk2(hv.x, hv.x);
                fma2(G[0][0], hp, wg.x); fma2(G[0][1], hp, wg.y);
                fma2(T[0][0], hp, wt.x); fma2(T[0][1], hp, wt.y);
                hp = pk2(hv.y, hv.y);
                fma2(G[1][0], hp, wg.x); fma2(G[1][1], hp, wg.y);
                fma2(T[1][0], hp, wt.x); fma2(T[1][1], hp, wt.y);
                hp = pk2(hv.z, hv.z);
                fma2(G[2][0], hp, wg.x); fma2(G[2][1], hp, wg.y);
                fma2(T[2][0], hp, wt.x); fma2(T[2][1], hp, wt.y);
                hp = pk2(hv.w, hv.w);
                fma2(G[3][0], hp, wg.x); fma2(G[3][1], hp, wg.y);
                fma2(T[3][0], hp, wt.x); fma2(T[3][1], hp, wt.y);
            }
            #pragma unroll
            for (int i = 0; i < 4; i++) {
                ulonglong2 tv; tv.x = T[i][0]; tv.y = T[i][1];
                *(ulonglong2*)&s_T[(v0 + i) * 64 + g0] = tv;
            }
            __syncthreads();

            u64 S[4][2];
            #pragma unroll
            for (int i = 0; i < 4; i++) { S[i][0] = 0ull; S[i][1] = 0ull; }
            #pragma unroll 4
            for (int u = 0; u < 64; u++) {
                ulonglong2 tp = *(const ulonglong2*)&s_T[u * 64 + g0];
                float4 av = *(const float4*)&s_aT[u * 68 + v0];
                u64 a;
                a = pk2(av.x, av.x); fma2(S[0][0], a, tp.x); fma2(S[0][1], a, tp.y);
                a = pk2(av.y, av.y); fma2(S[1][0], a, tp.x); fma2(S[1][1], a, tp.y);
                a = pk2(av.z, av.z); fma2(S[2][0], a, tp.x); fma2(S[2][1], a, tp.y);
                a = pk2(av.w, av.w); fma2(S[3][0], a, tp.x); fma2(S[3][1], a, tp.y);
            }
            float x[4][4];
            #pragma unroll
            for (int i = 0; i < 4; i++) {
                ulonglong2 e = *(const ulonglong2*)&s_et[(v0 + i) * 64 + g0];
                add2(G[i][0], S[i][0]); add2(G[i][1], S[i][1]);
                add2(G[i][0], e.x);     add2(G[i][1], e.y);
                up2(G[i][0], x[i][0], x[i][1]);
                up2(G[i][1], x[i][2], x[i][3]);
                x[i][0] = fmaxf(x[i][0], 0.f); x[i][1] = fmaxf(x[i][1], 0.f);
                x[i][2] = fmaxf(x[i][2], 0.f); x[i][3] = fmaxf(x[i][3], 0.f);
            }
            #pragma unroll
            for (int jj = 0; jj < 4; jj++) {
                float4 old = *(const float4*)&s_hT[(g0 + jj) * 68 + v0];
                float4 nv;
                nv.x = (mk[0] != 0.f) ? x[0][jj] : old.x;
                nv.y = (mk[1] != 0.f) ? x[1][jj] : old.y;
                nv.z = (mk[2] != 0.f) ? x[2][jj] : old.z;
                nv.w = (mk[3] != 0.f) ? x[3][jj] : old.w;
                *(float4*)&s_hT[(g0 + jj) * 68 + v0] = nv;
            }
            __syncthreads();
        }

        // ---- readout: out[o] = sum_v mask * relu(h@Wr_top + nr) ----
        for (int i4 = tid; i4 < 2048; i4 += 256)
            *(float4*)&s_W[i4 * 4] = *(const float4*)&W_r[i4 * 4];   // Wr top
        __syncthreads();

        u64 acc[8][2];
        #pragma unroll
        for (int vv = 0; vv < 8; vv++) {
            float4 f = __ldcg((const float4*)&g_nr[(long)(b * 64 + v0r + vv) * 128 + o0]);
            acc[vv][0] = pk2(f.x, f.y);
            acc[vv][1] = pk2(f.z, f.w);
        }
        #pragma unroll 2
        for (int k = 0; k < 64; k++) {
            ulonglong2 q = *(const ulonglong2*)&s_W[k * 128 + o0];
            float4 h0 = *(const float4*)&s_hT[k * 68 + v0r];
            float4 h1 = *(const float4*)&s_hT[k * 68 + v0r + 4];
            u64 hp;
            hp = pk2(h0.x, h0.x); fma2(acc[0][0], hp, q.x); fma2(acc[0][1], hp, q.y);
            hp = pk2(h0.y, h0.y); fma2(acc[1][0], hp, q.x); fma2(acc[1][1], hp, q.y);
            hp = pk2(h0.z, h0.z); fma2(acc[2][0], hp, q.x); fma2(acc[2][1], hp, q.y);
            hp = pk2(h0.w, h0.w); fma2(acc[3][0], hp, q.x); fma2(acc[3][1], hp, q.y);
            hp = pk2(h1.x, h1.x); fma2(acc[4][0], hp, q.x); fma2(acc[4][1], hp, q.y);
            hp = pk2(h1.y, h1.y); fma2(acc[5][0], hp, q.x); fma2(acc[5][1], hp, q.y);
            hp = pk2(h1.z, h1.z); fma2(acc[6][0], hp, q.x); fma2(acc[6][1], hp, q.y);
            hp = pk2(h1.w, h1.w); fma2(acc[7][0], hp, q.x); fma2(acc[7][1], hp, q.y);
        }
        float oa[4] = {0.f, 0.f, 0.f, 0.f};
        #pragma unroll
        for (int vv = 0; vv < 8; vv++) {
            if (s_mask[v0r + vv] != 0.f) {
                float y0, y1, y2, y3;
                up2(acc[vv][0], y0, y1); up2(acc[vv][1], y2, y3);
                oa[0] += fmaxf(y0, 0.f); oa[1] += fmaxf(y1, 0.f);
                oa[2] += fmaxf(y2, 0.f); oa[3] += fmaxf(y3, 0.f);
            }
        }
        __syncthreads();
        *(float4*)&s_red[ry * 128 + o0] = make_float4(oa[0], oa[1], oa[2], oa[3]);
        __syncthreads();
        if (tid < 128) {
            float s = 0.f;
            #pragma unroll
            for (int tt = 0; tt < 8; tt++) s += s_red[tt * 128 + tid];
            out[b * 128 + tid] = s;
        }
        __syncthreads();
    }
}

// ---------------------------------------------------------------------------
// Launch: ONE kernel, grid MUST be 296 (pad accounting depends on it).
// ---------------------------------------------------------------------------
extern "C" void kernel_launch(void* const* d_in, const int* in_sizes, int n_in,
                              void* d_out, int out_size)
{
    const int*   adj   = (const int*)  d_in[0];
    const float* nodes = (const float*)d_in[1];
    const float* edges = (const float*)d_in[2];
    const float* W_n   = (const float*)d_in[3];
    const float* W_e   = (const float*)d_in[4];
    const float* b_m   = (const float*)d_in[5];
    const float* W_u   = (const float*)d_in[6];
    const float* b_u   = (const float*)d_in[7];
    const float* W_r   = (const float*)d_in[8];
    const float* b_r   = (const float*)d_in[9];
    float* out = (float*)d_out;

    cudaFuncSetAttribute(k_mpnn, cudaFuncAttributeMaxDynamicSharedMemorySize,
                         SMEM_BYTES);

    k_mpnn<<<296, 256, SMEM_BYTES>>>(adj, nodes, edges, W_n, W_e, b_m,
                                     W_u, b_u, W_r, b_r, out);
}

// round 12
// speedup vs baseline: 1.8655x; 1.8655x over previous
#include <cuda_runtime.h>

typedef unsigned long long u64;

__device__ float g_agg[1024 * 64 * 16];    // raw edge aggregation (4 MB)
__device__ float g_nr [1024 * 64 * 128];   // nodes @ W_r_bot + b_r (32 MB)
__device__ float g_Wnb[64 * 64];
__device__ float g_Weu[16 * 64];
__device__ float g_cu [64];
__device__ unsigned g_ctr;

__device__ __forceinline__ u64 pk2(float lo, float hi) {
    u64 r; asm("mov.b64 %0, {%1, %2};" : "=l"(r) : "f"(lo), "f"(hi)); return r;
}
__device__ __forceinline__ void fma2(u64 &d, u64 a, u64 b) {
    asm("fma.rn.f32x2 %0, %1, %2, %0;" : "+l"(d) : "l"(a), "l"(b));
}
__device__ __forceinline__ void add2(u64 &d, u64 a) {
    asm("add.rn.f32x2 %0, %0, %1;" : "+l"(d) : "l"(a));
}
__device__ __forceinline__ void up2(u64 v, float &lo, float &hi) {
    asm("mov.b64 {%0, %1}, %2;" : "=f"(lo), "=f"(hi) : "l"(v));
}

// ---------------------------------------------------------------------------
// k_pre: blocks 0..2047 edge-agg (2 rows/warp-iter) + nr GEMM (DRAM-shadowed);
//        blocks 2048..2056 weight folds + counter reset. No cross-deps.
// ---------------------------------------------------------------------------
__global__ void __launch_bounds__(256)
k_pre(const int* __restrict__ adj, const float* __restrict__ edges,
      const float* __restrict__ nodes,
      const float* __restrict__ W_n, const float* __restrict__ W_e,
      const float* __restrict__ b_m, const float* __restrict__ W_u,
      const float* __restrict__ b_u,
      const float* __restrict__ W_r, const float* __restrict__ b_r)
{
    __shared__ float buf[8192 + 2048];   // 40 KB
    int bx = blockIdx.x, tid = threadIdx.x;

    if (bx < 2048) {
        float* s_Wr   = buf;             // W_r rows 64..127 (8192)
        float* s_nrow = buf + 8192;      // 8 warps x 2 x 64
        for (int i = tid; i < 8192; i += 256) s_Wr[i] = W_r[8192 + i];
        __syncthreads();

        int w = tid >> 5, lane = tid & 31;
        #pragma unroll
        for (int t = 0; t < 4; t += 2) {
            int bv0 = bx * 32 + t * 8 + w;
            int bv1 = bv0 + 8;
            const int*   a0 = adj + bv0 * 64;
            const int*   a1 = adj + bv1 * 64;
            const float* e0 = edges + (long)bv0 * 1024;
            const float* e1 = edges + (long)bv1 * 1024;

            float A0[16], A1[16];
            #pragma unroll
            for (int e = 0; e < 16; e++) { A0[e] = 0.f; A1[e] = 0.f; }
            #pragma unroll
            for (int s = 0; s < 2; s++) {
                int u = lane + s * 32;
                if (a0[u] != 0) {
                    const float4* e4 = (const float4*)(e0 + u * 16);
                    float4 x0 = e4[0], x1 = e4[1], x2 = e4[2], x3 = e4[3];
                    A0[0]+=x0.x; A0[1]+=x0.y; A0[2] +=x0.z; A0[3] +=x0.w;
                    A0[4]+=x1.x; A0[5]+=x1.y; A0[6] +=x1.z; A0[7] +=x1.w;
                    A0[8]+=x2.x; A0[9]+=x2.y; A0[10]+=x2.z; A0[11]+=x2.w;
                    A0[12]+=x3.x;A0[13]+=x3.y;A0[14]+=x3.z; A0[15]+=x3.w;
                }
                if (a1[u] != 0) {
                    const float4* e4 = (const float4*)(e1 + u * 16);
                    float4 x0 = e4[0], x1 = e4[1], x2 = e4[2], x3 = e4[3];
                    A1[0]+=x0.x; A1[1]+=x0.y; A1[2] +=x0.z; A1[3] +=x0.w;
                    A1[4]+=x1.x; A1[5]+=x1.y; A1[6] +=x1.z; A1[7] +=x1.w;
                    A1[8]+=x2.x; A1[9]+=x2.y; A1[10]+=x2.z; A1[11]+=x2.w;
                    A1[12]+=x3.x;A1[13]+=x3.y;A1[14]+=x3.z; A1[15]+=x3.w;
                }
            }
            #pragma unroll
            for (int off = 16; off > 0; off >>= 1) {
                #pragma unroll
                for (int e = 0; e < 16; e++) {
                    A0[e] += __shfl_xor_sync(0xffffffffu, A0[e], off);
                    A1[e] += __shfl_xor_sync(0xffffffffu, A1[e], off);
                }
            }
            if (lane == 0) {
                float4* d0 = (float4*)(g_agg + bv0 * 16);
                d0[0] = make_float4(A0[0],  A0[1],  A0[2],  A0[3]);
                d0[1] = make_float4(A0[4],  A0[5],  A0[6],  A0[7]);
                d0[2] = make_float4(A0[8],  A0[9],  A0[10], A0[11]);
                d0[3] = make_float4(A0[12], A0[13], A0[14], A0[15]);
                float4* d1 = (float4*)(g_agg + bv1 * 16);
                d1[0] = make_float4(A1[0],  A1[1],  A1[2],  A1[3]);
                d1[1] = make_float4(A1[4],  A1[5],  A1[6],  A1[7]);
                d1[2] = make_float4(A1[8],  A1[9],  A1[10], A1[11]);
                d1[3] = make_float4(A1[12], A1[13], A1[14], A1[15]);
            }

            // nr = nodes_row @ Wr_bot + b_r  for both rows (proven in R10)
            s_nrow[w * 128 + lane]       = nodes[bv0 * 64 + lane];
            s_nrow[w * 128 + lane + 32]  = nodes[bv0 * 64 + lane + 32];
            s_nrow[w * 128 + 64 + lane]      = nodes[bv1 * 64 + lane];
            s_nrow[w * 128 + 64 + lane + 32] = nodes[bv1 * 64 + lane + 32];
            __syncwarp();
            ulonglong2 r0 = *(const ulonglong2*)&b_r[lane * 4];
            ulonglong2 r1 = r0;
            #pragma unroll 4
            for (int k = 0; k < 64; k++) {
                float n0 = s_nrow[w * 128 + k];
                float n1 = s_nrow[w * 128 + 64 + k];
                ulonglong2 w2 = *(const ulonglong2*)&s_Wr[k * 128 + lane * 4];
                u64 p0 = pk2(n0, n0), p1 = pk2(n1, n1);
                fma2(r0.x, p0, w2.x); fma2(r0.y, p0, w2.y);
                fma2(r1.x, p1, w2.x); fma2(r1.y, p1, w2.y);
            }
            *(ulonglong2*)&g_nr[(long)bv0 * 128 + lane * 4] = r0;
            *(ulonglong2*)&g_nr[(long)bv1 * 128 + lane * 4] = r1;
            __syncwarp();
        }
    } else {
        float* s_Wu = buf;
        float* s_A  = buf + 8192;
        for (int i = tid; i < 8192; i += 256) s_Wu[i] = W_u[4096 + i];

        if (bx < 2056) {
            int r0 = (bx - 2048) * 8;
            for (int i = tid; i < 1024; i += 256) s_A[i] = W_n[r0 * 128 + i];
            __syncthreads();
            int g = tid & 63, r = tid >> 6;
            for (int rr = r; rr < 8; rr += 4) {
                float acc = 0.f;
                #pragma unroll 8
                for (int m = 0; m < 128; m++)
                    acc += s_A[rr * 128 + m] * s_Wu[m * 64 + g];
                g_Wnb[(r0 + rr) * 64 + g] = acc;
            }
        } else {
            if (tid == 0) g_ctr = 0u;
            for (int i = tid; i < 2048; i += 256) s_A[i] = W_e[i];
            __syncthreads();
            int g = tid & 63, r = tid >> 6;
            for (int rr = r; rr < 16; rr += 4) {
                float acc = 0.f;
                #pragma unroll 8
                for (int m = 0; m < 128; m++)
                    acc += s_A[rr * 128 + m] * s_Wu[m * 64 + g];
                g_Weu[rr * 64 + g] = acc;
            }
            if (tid < 64) {
                float acc = b_u[tid];
                #pragma unroll 8
                for (int m = 0; m < 128; m++)
                    acc += b_m[m] * s_Wu[m * 64 + tid];
                g_cu[tid] = acc;
            }
        }
    }
}

// ---------------------------------------------------------------------------
// k_mpnn: persistent CTAs; 4 passes (proven R7 core) + HALF readout (nr
// preaccumulated in g_nr). smem layout as R7: 25408 floats -> 2 CTAs/SM.
// ---------------------------------------------------------------------------
#define SMEM_BYTES (25408 * 4)

__global__ void __launch_bounds__(256, 2)
k_mpnn(const int* __restrict__ adj, const float* __restrict__ nodes,
       const float* __restrict__ W_u, const float* __restrict__ W_r,
       float* __restrict__ out)
{
    extern __shared__ float sm[];
    float* s_hT   = sm;
    float* s_W    = sm + 4352;
    float* s_aT   = sm + 12544;
    float* s_T    = sm + 16896;
    float* s_et   = sm + 20992;
    float* s_mask = sm + 25344;
    float* s_red  = s_W;
    __shared__ unsigned s_b;

    int tid = threadIdx.x;
    const int tx = tid & 15, ty = tid >> 4;     // passes: 4v x 4g
    const int g0 = tx * 4,   v0 = ty * 4;
    const int rx = tid & 31, ry = tid >> 5;     // readout: 8v x 4o
    const int o0 = rx * 4,   v0r = ry * 8;

    while (true) {
        if (tid == 0) s_b = atomicAdd(&g_ctr, 1u);
        __syncthreads();
        unsigned b = s_b;
        if (b >= 1024u) break;

        const float* nb = nodes + b * 4096;
        const int*   ab = adj   + b * 4096;
        for (int i4 = tid; i4 < 1024; i4 += 256) {
            int v = i4 >> 4, f = (i4 & 15) * 4;
            float4 hv = *(const float4*)&nb[v * 64 + f];
            s_hT[(f + 0) * 68 + v] = hv.x;
            s_hT[(f + 1) * 68 + v] = hv.y;
            s_hT[(f + 2) * 68 + v] = hv.z;
            s_hT[(f + 3) * 68 + v] = hv.w;
            int4 a4 = *(const int4*)&ab[v * 64 + f];
            s_aT[(f + 0) * 68 + v] = (float)a4.x;
            s_aT[(f + 1) * 68 + v] = (float)a4.y;
            s_aT[(f + 2) * 68 + v] = (float)a4.z;
            s_aT[(f + 3) * 68 + v] = (float)a4.w;
        }
        for (int i4 = tid; i4 < 2048; i4 += 256) {
            int f = i4 >> 5, gq = (i4 & 31) * 4;
            *(float4*)&s_W[f * 128 + gq] = (gq < 64)
                ? *(const float4*)&W_u[f * 64 + gq]
                : *(const float4*)&g_Wnb[f * 64 + gq - 64];
        }
        for (int i = tid; i < 1024; i += 256) {
            s_T[i]        = g_agg[(long)b * 1024 + i];
            s_T[1024 + i] = g_Weu[i];
        }
        if (tid < 64) s_T[2048 + tid] = g_cu[tid];
        __syncthreads();

        if (tid < 64) {
            float s = 0.f;
            #pragma unroll 8
            for (int u = 0; u < 64; u++) s += s_aT[u * 68 + tid];
            s_mask[tid] = (s > 0.f) ? 1.f : 0.f;
        }
        // et2[v][g] = cu[g] + agg[v][:] @ Weu[:, g]
        {
            float4 cu4 = *(const float4*)&s_T[2048 + g0];
            #pragma unroll
            for (int i = 0; i < 4; i++) {
                float e0 = cu4.x, e1 = cu4.y, e2 = cu4.z, e3 = cu4.w;
                #pragma unroll
                for (int e = 0; e < 16; e++) {
                    float a = s_T[(v0 + i) * 16 + e];
                    float4 u4 = *(const float4*)&s_T[1024 + e * 64 + g0];
                    e0 += a * u4.x; e1 += a * u4.y; e2 += a * u4.z; e3 += a * u4.w;
                }
                *(float4*)&s_et[(v0 + i) * 64 + g0] = make_float4(e0, e1, e2, e3);
            }
        }
        __syncthreads();
        float mk[4];
        #pragma unroll
        for (int i = 0; i < 4; i++) mk[i] = s_mask[v0 + i];

        // ---- 4 message passes (R7 core, unchanged) ----
        for (int pass = 0; pass < 4; pass++) {
            u64 G[4][2], T[4][2];
            #pragma unroll
            for (int i = 0; i < 4; i++) {
                G[i][0] = 0ull; G[i][1] = 0ull;
                T[i][0] = 0ull; T[i][1] = 0ull;
            }
            #pragma unroll 4
            for (int f = 0; f < 64; f++) {
                ulonglong2 wg = *(const ulonglong2*)&s_W[f * 128 + g0];
                ulonglong2 wt = *(const ulonglong2*)&s_W[f * 128 + 64 + g0];
                float4 hv = *(const float4*)&s_hT[f * 68 + v0];
                u64 hp;
                hp = pk2(hv.x, hv.x);
                fma2(G[0][0], hp, wg.x); fma2(G[0][1], hp, wg.y);
                fma2(T[0][0], hp, wt.x); fma2(T[0][1], hp, wt.y);
                hp = pk2(hv.y, hv.y);
                fma2(G[1][0], hp, wg.x); fma2(G[1][1], hp, wg.y);
                fma2(T[1][0], hp, wt.x); fma2(T[1][1], hp, wt.y);
                hp = pk2(hv.z, hv.z);
                fma2(G[2][0], hp, wg.x); fma2(G[2][1], hp, wg.y);
                fma2(T[2][0], hp, wt.x); fma2(T[2][1], hp, wt.y);
                hp = pk2(hv.w, hv.w);
                fma2(G[3][0], hp, wg.x); fma2(G[3][1], hp, wg.y);
                fma2(T[3][0], hp, wt.x); fma2(T[3][1], hp, wt.y);
            }
            #pragma unroll
            for (int i = 0; i < 4; i++) {
                ulonglong2 tv; tv.x = T[i][0]; tv.y = T[i][1];
                *(ulonglong2*)&s_T[(v0 + i) * 64 + g0] = tv;
            }
            __syncthreads();

            u64 S[4][2];
            #pragma unroll
            for (int i = 0; i < 4; i++) { S[i][0] = 0ull; S[i][1] = 0ull; }
            #pragma unroll 4
            for (int u = 0; u < 64; u++) {
                ulonglong2 tp = *(const ulonglong2*)&s_T[u * 64 + g0];
                float4 av = *(const float4*)&s_aT[u * 68 + v0];
                u64 a;
                a = pk2(av.x, av.x); fma2(S[0][0], a, tp.x); fma2(S[0][1], a, tp.y);
                a = pk2(av.y, av.y); fma2(S[1][0], a, tp.x); fma2(S[1][1], a, tp.y);
                a = pk2(av.z, av.z); fma2(S[2][0], a, tp.x); fma2(S[2][1], a, tp.y);
                a = pk2(av.w, av.w); fma2(S[3][0], a, tp.x); fma2(S[3][1], a, tp.y);
            }
            float x[4][4];
            #pragma unroll
            for (int i = 0; i < 4; i++) {
                ulonglong2 e = *(const ulonglong2*)&s_et[(v0 + i) * 64 + g0];
                add2(G[i][0], S[i][0]); add2(G[i][1], S[i][1]);
                add2(G[i][0], e.x);     add2(G[i][1], e.y);
                up2(G[i][0], x[i][0], x[i][1]);
                up2(G[i][1], x[i][2], x[i][3]);
                x[i][0] = fmaxf(x[i][0], 0.f); x[i][1] = fmaxf(x[i][1], 0.f);
                x[i][2] = fmaxf(x[i][2], 0.f); x[i][3] = fmaxf(x[i][3], 0.f);
            }
            #pragma unroll
            for (int j = 0; j < 4; j++) {
                float4 old = *(const float4*)&s_hT[(g0 + j) * 68 + v0];
                float4 nv;
                nv.x = (mk[0] != 0.f) ? x[0][j] : old.x;
                nv.y = (mk[1] != 0.f) ? x[1][j] : old.y;
                nv.z = (mk[2] != 0.f) ? x[2][j] : old.z;
                nv.w = (mk[3] != 0.f) ? x[3][j] : old.w;
                *(float4*)&s_hT[(g0 + j) * 68 + v0] = nv;
            }
            __syncthreads();
        }

        // ---- readout: out[o] = sum_v mask * relu(h@Wr_top + nr) ----
        for (int i4 = tid; i4 < 2048; i4 += 256)
            *(float4*)&s_W[i4 * 4] = *(const float4*)&W_r[i4 * 4];   // Wr top
        __syncthreads();

        u64 acc[8][2];
        #pragma unroll
        for (int vv = 0; vv < 8; vv++) {
            float4 f = __ldcg((const float4*)&g_nr[(long)(b * 64 + v0r + vv) * 128 + o0]);
            acc[vv][0] = pk2(f.x, f.y);
            acc[vv][1] = pk2(f.z, f.w);
        }
        #pragma unroll 2
        for (int k = 0; k < 64; k++) {
            ulonglong2 q = *(const ulonglong2*)&s_W[k * 128 + o0];
            float4 h0 = *(const float4*)&s_hT[k * 68 + v0r];
            float4 h1 = *(const float4*)&s_hT[k * 68 + v0r + 4];
            u64 hp;
            hp = pk2(h0.x, h0.x); fma2(acc[0][0], hp, q.x); fma2(acc[0][1], hp, q.y);
            hp = pk2(h0.y, h0.y); fma2(acc[1][0], hp, q.x); fma2(acc[1][1], hp, q.y);
            hp = pk2(h0.z, h0.z); fma2(acc[2][0], hp, q.x); fma2(acc[2][1], hp, q.y);
            hp = pk2(h0.w, h0.w); fma2(acc[3][0], hp, q.x); fma2(acc[3][1], hp, q.y);
            hp = pk2(h1.x, h1.x); fma2(acc[4][0], hp, q.x); fma2(acc[4][1], hp, q.y);
            hp = pk2(h1.y, h1.y); fma2(acc[5][0], hp, q.x); fma2(acc[5][1], hp, q.y);
            hp = pk2(h1.z, h1.z); fma2(acc[6][0], hp, q.x); fma2(acc[6][1], hp, q.y);
            hp = pk2(h1.w, h1.w); fma2(acc[7][0], hp, q.x); fma2(acc[7][1], hp, q.y);
        }
        float oa[4] = {0.f, 0.f, 0.f, 0.f};
        #pragma unroll
        for (int vv = 0; vv < 8; vv++) {
            if (s_mask[v0r + vv] != 0.f) {
                float y0, y1, y2, y3;
                up2(acc[vv][0], y0, y1); up2(acc[vv][1], y2, y3);
                oa[0] += fmaxf(y0, 0.f); oa[1] += fmaxf(y1, 0.f);
                oa[2] += fmaxf(y2, 0.f); oa[3] += fmaxf(y3, 0.f);
            }
        }
        __syncthreads();
        *(float4*)&s_red[ry * 128 + o0] = make_float4(oa[0], oa[1], oa[2], oa[3]);
        __syncthreads();
        if (tid < 128) {
            float s = 0.f;
            #pragma unroll
            for (int t = 0; t < 8; t++) s += s_red[t * 128 + tid];
            out[b * 128 + tid] = s;
        }
        __syncthreads();
    }
}

// ---------------------------------------------------------------------------
// Launch
// ---------------------------------------------------------------------------
extern "C" void kernel_launch(void* const* d_in, const int* in_sizes, int n_in,
                              void* d_out, int out_size)
{
    const int*   adj   = (const int*)  d_in[0];
    const float* nodes = (const float*)d_in[1];
    const float* edges = (const float*)d_in[2];
    const float* W_n   = (const float*)d_in[3];
    const float* W_e   = (const float*)d_in[4];
    const float* b_m   = (const float*)d_in[5];
    const float* W_u   = (const float*)d_in[6];
    const float* b_u   = (const float*)d_in[7];
    const float* W_r   = (const float*)d_in[8];
    const float* b_r   = (const float*)d_in[9];
    float* out = (float*)d_out;

    cudaFuncSetAttribute(k_mpnn, cudaFuncAttributeMaxDynamicSharedMemorySize,
                         SMEM_BYTES);

    k_pre<<<2057, 256>>>(adj, edges, nodes, W_n, W_e, b_m, W_u, b_u, W_r, b_r);
    k_mpnn<<<296, 256, SMEM_BYTES>>>(adj, nodes, W_u, W_r, out);
}

// round 13
// speedup vs baseline: 1.9237x; 1.0312x over previous
#include <cuda_runtime.h>

typedef unsigned long long u64;

__device__ float g_agg[1024 * 64 * 16];    // raw edge aggregation (4 MB)
__device__ float g_nr [1024 * 64 * 128];   // nodes @ W_r_bot + b_r (32 MB)
__device__ float g_Wnb[64 * 64];
__device__ float g_Weu[16 * 64];
__device__ float g_cu [64];
__device__ unsigned g_ctr;

__device__ __forceinline__ u64 pk2(float lo, float hi) {
    u64 r; asm("mov.b64 %0, {%1, %2};" : "=l"(r) : "f"(lo), "f"(hi)); return r;
}
__device__ __forceinline__ void fma2(u64 &d, u64 a, u64 b) {
    asm("fma.rn.f32x2 %0, %1, %2, %0;" : "+l"(d) : "l"(a), "l"(b));
}
__device__ __forceinline__ void add2(u64 &d, u64 a) {
    asm("add.rn.f32x2 %0, %0, %1;" : "+l"(d) : "l"(a));
}
__device__ __forceinline__ void up2(u64 v, float &lo, float &hi) {
    asm("mov.b64 {%0, %1}, %2;" : "=f"(lo), "=f"(hi) : "l"(v));
}

// ---------------------------------------------------------------------------
// k_pre, role-split grid (3081 blocks):
//   0..2047    : edge aggregation (R6-proven code, DRAM-bound)
//   2048..3071 : nr = nodes @ W_r_bot + b_r, one batch per block (fma-bound,
//                overlaps edge blocks via HW co-residency)
//   3072..3080 : weight folds + counter reset
// ---------------------------------------------------------------------------
__global__ void __launch_bounds__(256)
k_pre(const int* __restrict__ adj, const float* __restrict__ edges,
      const float* __restrict__ nodes,
      const float* __restrict__ W_n, const float* __restrict__ W_e,
      const float* __restrict__ b_m, const float* __restrict__ W_u,
      const float* __restrict__ b_u,
      const float* __restrict__ W_r, const float* __restrict__ b_r)
{
    __shared__ float buf[12288];   // 48 KB
    int bx = blockIdx.x, tid = threadIdx.x;
    int w = tid >> 5, lane = tid & 31;

    if (bx < 2048) {
        // ---- edge aggregation (byte-identical to R6 k_edge inner) ----
        for (int t = 0; t < 4; t++) {
            int bv = bx * 32 + t * 8 + w;
            const int*   arow = adj   + bv * 64;
            const float* erow = edges + (long)bv * 1024;

            float acc[16];
            #pragma unroll
            for (int e = 0; e < 16; e++) acc[e] = 0.f;
            #pragma unroll
            for (int s = 0; s < 2; s++) {
                int u = lane + s * 32;
                if (arow[u] != 0) {
                    const float4* e4 = (const float4*)(erow + u * 16);
                    float4 x0 = e4[0], x1 = e4[1], x2 = e4[2], x3 = e4[3];
                    acc[0] += x0.x;  acc[1] += x0.y;  acc[2]  += x0.z;  acc[3]  += x0.w;
                    acc[4] += x1.x;  acc[5] += x1.y;  acc[6]  += x1.z;  acc[7]  += x1.w;
                    acc[8] += x2.x;  acc[9] += x2.y;  acc[10] += x2.z;  acc[11] += x2.w;
                    acc[12]+= x3.x;  acc[13]+= x3.y;  acc[14] += x3.z;  acc[15] += x3.w;
                }
            }
            #pragma unroll
            for (int off = 16; off > 0; off >>= 1) {
                #pragma unroll
                for (int e = 0; e < 16; e++)
                    acc[e] += __shfl_xor_sync(0xffffffffu, acc[e], off);
            }
            if (lane == 0) {
                float4* dst = (float4*)(g_agg + bv * 16);
                dst[0] = make_float4(acc[0],  acc[1],  acc[2],  acc[3]);
                dst[1] = make_float4(acc[4],  acc[5],  acc[6],  acc[7]);
                dst[2] = make_float4(acc[8],  acc[9],  acc[10], acc[11]);
                dst[3] = make_float4(acc[12], acc[13], acc[14], acc[15]);
            }
        }
    } else if (bx < 3072) {
        // ---- nr block: one batch, 64 rows x 128 outs ----
        int b = bx - 2048;
        float* s_Wr = buf;           // 8192 : W_r rows 64..127
        float* s_nd = buf + 8192;    // 4096 : nodes[b]
        for (int i4 = tid; i4 < 2048; i4 += 256)
            *(float4*)&s_Wr[i4 * 4] = *(const float4*)&W_r[8192 + i4 * 4];
        for (int i4 = tid; i4 < 1024; i4 += 256)
            *(float4*)&s_nd[i4 * 4] = *(const float4*)&nodes[(long)b * 4096 + i4 * 4];
        __syncthreads();

        const int rx = tid & 31, ry = tid >> 5;
        const int o0 = rx * 4, v0r = ry * 8;
        u64 acc[8][2];
        {
            ulonglong2 br = *(const ulonglong2*)&b_r[o0];
            #pragma unroll
            for (int vv = 0; vv < 8; vv++) { acc[vv][0] = br.x; acc[vv][1] = br.y; }
        }
        #pragma unroll 2
        for (int k = 0; k < 64; k++) {
            ulonglong2 q = *(const ulonglong2*)&s_Wr[k * 128 + o0];
            #pragma unroll
            for (int vv = 0; vv < 8; vv++) {
                float nv = s_nd[(v0r + vv) * 64 + k];
                u64 np = pk2(nv, nv);
                fma2(acc[vv][0], np, q.x); fma2(acc[vv][1], np, q.y);
            }
        }
        #pragma unroll
        for (int vv = 0; vv < 8; vv++) {
            ulonglong2 o; o.x = acc[vv][0]; o.y = acc[vv][1];
            *(ulonglong2*)&g_nr[(long)(b * 64 + v0r + vv) * 128 + o0] = o;
        }
    } else {
        // ---- fold blocks ----
        float* s_Wu = buf;
        float* s_A  = buf + 8192;
        for (int i = tid; i < 8192; i += 256) s_Wu[i] = W_u[4096 + i];

        if (bx < 3080) {
            int r0 = (bx - 3072) * 8;
            for (int i = tid; i < 1024; i += 256) s_A[i] = W_n[r0 * 128 + i];
            __syncthreads();
            int g = tid & 63, r = tid >> 6;
            for (int rr = r; rr < 8; rr += 4) {
                float acc = 0.f;
                #pragma unroll 8
                for (int m = 0; m < 128; m++)
                    acc += s_A[rr * 128 + m] * s_Wu[m * 64 + g];
                g_Wnb[(r0 + rr) * 64 + g] = acc;
            }
        } else {
            if (tid == 0) g_ctr = 0u;
            for (int i = tid; i < 2048; i += 256) s_A[i] = W_e[i];
            __syncthreads();
            int g = tid & 63, r = tid >> 6;
            for (int rr = r; rr < 16; rr += 4) {
                float acc = 0.f;
                #pragma unroll 8
                for (int m = 0; m < 128; m++)
                    acc += s_A[rr * 128 + m] * s_Wu[m * 64 + g];
                g_Weu[rr * 64 + g] = acc;
            }
            if (tid < 64) {
                float acc = b_u[tid];
                #pragma unroll 8
                for (int m = 0; m < 128; m++)
                    acc += b_m[m] * s_Wu[m * 64 + tid];
                g_cu[tid] = acc;
            }
        }
    }
}

// ---------------------------------------------------------------------------
// k_mpnn: IDENTICAL to R12 (measured 187.9us, rel_err 5.6e-7).
// ---------------------------------------------------------------------------
#define SMEM_BYTES (25408 * 4)

__global__ void __launch_bounds__(256, 2)
k_mpnn(const int* __restrict__ adj, const float* __restrict__ nodes,
       const float* __restrict__ W_u, const float* __restrict__ W_r,
       float* __restrict__ out)
{
    extern __shared__ float sm[];
    float* s_hT   = sm;
    float* s_W    = sm + 4352;
    float* s_aT   = sm + 12544;
    float* s_T    = sm + 16896;
    float* s_et   = sm + 20992;
    float* s_mask = sm + 25344;
    float* s_red  = s_W;
    __shared__ unsigned s_b;

    int tid = threadIdx.x;
    const int tx = tid & 15, ty = tid >> 4;
    const int g0 = tx * 4,   v0 = ty * 4;
    const int rx = tid & 31, ry = tid >> 5;
    const int o0 = rx * 4,   v0r = ry * 8;

    while (true) {
        if (tid == 0) s_b = atomicAdd(&g_ctr, 1u);
        __syncthreads();
        unsigned b = s_b;
        if (b >= 1024u) break;

        const float* nb = nodes + b * 4096;
        const int*   ab = adj   + b * 4096;
        for (int i4 = tid; i4 < 1024; i4 += 256) {
            int v = i4 >> 4, f = (i4 & 15) * 4;
            float4 hv = *(const float4*)&nb[v * 64 + f];
            s_hT[(f + 0) * 68 + v] = hv.x;
            s_hT[(f + 1) * 68 + v] = hv.y;
            s_hT[(f + 2) * 68 + v] = hv.z;
            s_hT[(f + 3) * 68 + v] = hv.w;
            int4 a4 = *(const int4*)&ab[v * 64 + f];
            s_aT[(f + 0) * 68 + v] = (float)a4.x;
            s_aT[(f + 1) * 68 + v] = (float)a4.y;
            s_aT[(f + 2) * 68 + v] = (float)a4.z;
            s_aT[(f + 3) * 68 + v] = (float)a4.w;
        }
        for (int i4 = tid; i4 < 2048; i4 += 256) {
            int f = i4 >> 5, gq = (i4 & 31) * 4;
            *(float4*)&s_W[f * 128 + gq] = (gq < 64)
                ? *(const float4*)&W_u[f * 64 + gq]
                : *(const float4*)&g_Wnb[f * 64 + gq - 64];
        }
        for (int i = tid; i < 1024; i += 256) {
            s_T[i]        = g_agg[(long)b * 1024 + i];
            s_T[1024 + i] = g_Weu[i];
        }
        if (tid < 64) s_T[2048 + tid] = g_cu[tid];
        __syncthreads();

        if (tid < 64) {
            float s = 0.f;
            #pragma unroll 8
            for (int u = 0; u < 64; u++) s += s_aT[u * 68 + tid];
            s_mask[tid] = (s > 0.f) ? 1.f : 0.f;
        }
        {
            float4 cu4 = *(const float4*)&s_T[2048 + g0];
            #pragma unroll
            for (int i = 0; i < 4; i++) {
                float e0 = cu4.x, e1 = cu4.y, e2 = cu4.z, e3 = cu4.w;
                #pragma unroll
                for (int e = 0; e < 16; e++) {
                    float a = s_T[(v0 + i) * 16 + e];
                    float4 u4 = *(const float4*)&s_T[1024 + e * 64 + g0];
                    e0 += a * u4.x; e1 += a * u4.y; e2 += a * u4.z; e3 += a * u4.w;
                }
                *(float4*)&s_et[(v0 + i) * 64 + g0] = make_float4(e0, e1, e2, e3);
            }
        }
        __syncthreads();
        float mk[4];
        #pragma unroll
        for (int i = 0; i < 4; i++) mk[i] = s_mask[v0 + i];

        for (int pass = 0; pass < 4; pass++) {
            u64 G[4][2], T[4][2];
            #pragma unroll
            for (int i = 0; i < 4; i++) {
                G[i][0] = 0ull; G[i][1] = 0ull;
                T[i][0] = 0ull; T[i][1] = 0ull;
            }
            #pragma unroll 4
            for (int f = 0; f < 64; f++) {
                ulonglong2 wg = *(const ulonglong2*)&s_W[f * 128 + g0];
                ulonglong2 wt = *(const ulonglong2*)&s_W[f * 128 + 64 + g0];
                float4 hv = *(const float4*)&s_hT[f * 68 + v0];
                u64 hp;
                hp = pk2(hv.x, hv.x);
                fma2(G[0][0], hp, wg.x); fma2(G[0][1], hp, wg.y);
                fma2(T[0][0], hp, wt.x); fma2(T[0][1], hp, wt.y);
                hp = pk2(hv.y, hv.y);
                fma2(G[1][0], hp, wg.x); fma2(G[1][1], hp, wg.y);
                fma2(T[1][0], hp, wt.x); fma2(T[1][1], hp, wt.y);
                hp = pk2(hv.z, hv.z);
                fma2(G[2][0], hp, wg.x); fma2(G[2][1], hp, wg.y);
                fma2(T[2][0], hp, wt.x); fma2(T[2][1], hp, wt.y);
                hp = pk2(hv.w, hv.w);
                fma2(G[3][0], hp, wg.x); fma2(G[3][1], hp, wg.y);
                fma2(T[3][0], hp, wt.x); fma2(T[3][1], hp, wt.y);
            }
            #pragma unroll
            for (int i = 0; i < 4; i++) {
                ulonglong2 tv; tv.x = T[i][0]; tv.y = T[i][1];
                *(ulonglong2*)&s_T[(v0 + i) * 64 + g0] = tv;
            }
            __syncthreads();

            u64 S[4][2];
            #pragma unroll
            for (int i = 0; i < 4; i++) { S[i][0] = 0ull; S[i][1] = 0ull; }
            #pragma unroll 4
            for (int u = 0; u < 64; u++) {
                ulonglong2 tp = *(const ulonglong2*)&s_T[u * 64 + g0];
                float4 av = *(const float4*)&s_aT[u * 68 + v0];
                u64 a;
                a = pk2(av.x, av.x); fma2(S[0][0], a, tp.x); fma2(S[0][1], a, tp.y);
                a = pk2(av.y, av.y); fma2(S[1][0], a, tp.x); fma2(S[1][1], a, tp.y);
                a = pk2(av.z, av.z); fma2(S[2][0], a, tp.x); fma2(S[2][1], a, tp.y);
                a = pk2(av.w, av.w); fma2(S[3][0], a, tp.x); fma2(S[3][1], a, tp.y);
            }
            float x[4][4];
            #pragma unroll
            for (int i = 0; i < 4; i++) {
                ulonglong2 e = *(const ulonglong2*)&s_et[(v0 + i) * 64 + g0];
                add2(G[i][0], S[i][0]); add2(G[i][1], S[i][1]);
                add2(G[i][0], e.x);     add2(G[i][1], e.y);
                up2(G[i][0], x[i][0], x[i][1]);
                up2(G[i][1], x[i][2], x[i][3]);
                x[i][0] = fmaxf(x[i][0], 0.f); x[i][1] = fmaxf(x[i][1], 0.f);
                x[i][2] = fmaxf(x[i][2], 0.f); x[i][3] = fmaxf(x[i][3], 0.f);
            }
            #pragma unroll
            for (int j = 0; j < 4; j++) {
                float4 old = *(const float4*)&s_hT[(g0 + j) * 68 + v0];
                float4 nv;
                nv.x = (mk[0] != 0.f) ? x[0][j] : old.x;
                nv.y = (mk[1] != 0.f) ? x[1][j] : old.y;
                nv.z = (mk[2] != 0.f) ? x[2][j] : old.z;
                nv.w = (mk[3] != 0.f) ? x[3][j] : old.w;
                *(float4*)&s_hT[(g0 + j) * 68 + v0] = nv;
            }
            __syncthreads();
        }

        for (int i4 = tid; i4 < 2048; i4 += 256)
            *(float4*)&s_W[i4 * 4] = *(const float4*)&W_r[i4 * 4];
        __syncthreads();

        u64 acc[8][2];
        #pragma unroll
        for (int vv = 0; vv < 8; vv++) {
            float4 f = __ldcg((const float4*)&g_nr[(long)(b * 64 + v0r + vv) * 128 + o0]);
            acc[vv][0] = pk2(f.x, f.y);
            acc[vv][1] = pk2(f.z, f.w);
        }
        #pragma unroll 2
        for (int k = 0; k < 64; k++) {
            ulonglong2 q = *(const ulonglong2*)&s_W[k * 128 + o0];
            float4 h0 = *(const float4*)&s_hT[k * 68 + v0r];
            float4 h1 = *(const float4*)&s_hT[k * 68 + v0r + 4];
            u64 hp;
            hp = pk2(h0.x, h0.x); fma2(acc[0][0], hp, q.x); fma2(acc[0][1], hp, q.y);
            hp = pk2(h0.y, h0.y); fma2(acc[1][0], hp, q.x); fma2(acc[1][1], hp, q.y);
            hp = pk2(h0.z, h0.z); fma2(acc[2][0], hp, q.x); fma2(acc[2][1], hp, q.y);
            hp = pk2(h0.w, h0.w); fma2(acc[3][0], hp, q.x); fma2(acc[3][1], hp, q.y);
            hp = pk2(h1.x, h1.x); fma2(acc[4][0], hp, q.x); fma2(acc[4][1], hp, q.y);
            hp = pk2(h1.y, h1.y); fma2(acc[5][0], hp, q.x); fma2(acc[5][1], hp, q.y);
            hp = pk2(h1.z, h1.z); fma2(acc[6][0], hp, q.x); fma2(acc[6][1], hp, q.y);
            hp = pk2(h1.w, h1.w); fma2(acc[7][0], hp, q.x); fma2(acc[7][1], hp, q.y);
        }
        float oa[4] = {0.f, 0.f, 0.f, 0.f};
        #pragma unroll
        for (int vv = 0; vv < 8; vv++) {
            if (s_mask[v0r + vv] != 0.f) {
                float y0, y1, y2, y3;
                up2(acc[vv][0], y0, y1); up2(acc[vv][1], y2, y3);
                oa[0] += fmaxf(y0, 0.f); oa[1] += fmaxf(y1, 0.f);
                oa[2] += fmaxf(y2, 0.f); oa[3] += fmaxf(y3, 0.f);
            }
        }
        __syncthreads();
        *(float4*)&s_red[ry * 128 + o0] = make_float4(oa[0], oa[1], oa[2], oa[3]);
        __syncthreads();
        if (tid < 128) {
            float s = 0.f;
            #pragma unroll
            for (int t = 0; t < 8; t++) s += s_red[t * 128 + tid];
            out[b * 128 + tid] = s;
        }
        __syncthreads();
    }
}

// ---------------------------------------------------------------------------
// Launch
// ---------------------------------------------------------------------------
extern "C" void kernel_launch(void* const* d_in, const int* in_sizes, int n_in,
                              void* d_out, int out_size)
{
    const int*   adj   = (const int*)  d_in[0];
    const float* nodes = (const float*)d_in[1];
    const float* edges = (const float*)d_in[2];
    const float* W_n   = (const float*)d_in[3];
    const float* W_e   = (const float*)d_in[4];
    const float* b_m   = (const float*)d_in[5];
    const float* W_u   = (const float*)d_in[6];
    const float* b_u   = (const float*)d_in[7];
    const float* W_r   = (const float*)d_in[8];
    const float* b_r   = (const float*)d_in[9];
    float* out = (float*)d_out;

    cudaFuncSetAttribute(k_mpnn, cudaFuncAttributeMaxDynamicSharedMemorySize,
                         SMEM_BYTES);

    k_pre<<<3081, 256>>>(adj, edges, nodes, W_n, W_e, b_m, W_u, b_u, W_r, b_r);
    k_mpnn<<<296, 256, SMEM_BYTES>>>(adj, nodes, W_u, W_r, out);
}

// round 15
// speedup vs baseline: 1.9916x; 1.0353x over previous
#include <cuda_runtime.h>

typedef unsigned long long u64;

__device__ float g_agg[1024 * 64 * 16];    // raw edge aggregation (4 MB)
__device__ float g_nr [1024 * 64 * 128];   // nodes @ W_r_bot + b_r (32 MB)
__device__ float g_Wnb[64 * 64];
__device__ float g_Weu[16 * 64];
__device__ float g_cu [64];
__device__ unsigned g_ctr;

__device__ __forceinline__ u64 pk2(float lo, float hi) {
    u64 r; asm("mov.b64 %0, {%1, %2};" : "=l"(r) : "f"(lo), "f"(hi)); return r;
}
__device__ __forceinline__ void fma2(u64 &d, u64 a, u64 b) {
    asm("fma.rn.f32x2 %0, %1, %2, %0;" : "+l"(d) : "l"(a), "l"(b));
}
__device__ __forceinline__ void add2(u64 &d, u64 a) {
    asm("add.rn.f32x2 %0, %0, %1;" : "+l"(d) : "l"(a));
}
__device__ __forceinline__ void up2(u64 v, float &lo, float &hi) {
    asm("mov.b64 {%0, %1}, %2;" : "=f"(lo), "=f"(hi) : "l"(v));
}

// ---------------------------------------------------------------------------
// k_pre, role-INTERLEAVED grid (3081 blocks):
//   bx < 3072, bx%3<2  : edge aggregation block  (e = (bx/3)*2 + bx%3)
//   bx < 3072, bx%3==2 : nr block (b = bx/3) -- co-resident with edge blocks,
//                        its fma hides under their DRAM latency
//   3072..3080         : weight folds + counter reset
// ---------------------------------------------------------------------------
__global__ void __launch_bounds__(256)
k_pre(const int* __restrict__ adj, const float* __restrict__ edges,
      const float* __restrict__ nodes,
      const float* __restrict__ W_n, const float* __restrict__ W_e,
      const float* __restrict__ b_m, const float* __restrict__ W_u,
      const float* __restrict__ b_u,
      const float* __restrict__ W_r, const float* __restrict__ b_r)
{
    __shared__ float buf[12288];   // 48 KB
    int bx = blockIdx.x, tid = threadIdx.x;
    int w = tid >> 5, lane = tid & 31;

    if (bx < 3072 && (bx % 3) < 2) {
        // ---- edge aggregation (byte-identical inner to R6/R13) ----
        int e = (bx / 3) * 2 + (bx % 3);
        for (int t = 0; t < 4; t++) {
            int bv = e * 32 + t * 8 + w;
            const int*   arow = adj   + bv * 64;
            const float* erow = edges + (long)bv * 1024;

            float acc[16];
            #pragma unroll
            for (int q = 0; q < 16; q++) acc[q] = 0.f;
            #pragma unroll
            for (int s = 0; s < 2; s++) {
                int u = lane + s * 32;
                if (arow[u] != 0) {
                    const float4* e4 = (const float4*)(erow + u * 16);
                    float4 x0 = e4[0], x1 = e4[1], x2 = e4[2], x3 = e4[3];
                    acc[0] += x0.x;  acc[1] += x0.y;  acc[2]  += x0.z;  acc[3]  += x0.w;
                    acc[4] += x1.x;  acc[5] += x1.y;  acc[6]  += x1.z;  acc[7]  += x1.w;
                    acc[8] += x2.x;  acc[9] += x2.y;  acc[10] += x2.z;  acc[11] += x2.w;
                    acc[12]+= x3.x;  acc[13]+= x3.y;  acc[14] += x3.z;  acc[15] += x3.w;
                }
            }
            #pragma unroll
            for (int off = 16; off > 0; off >>= 1) {
                #pragma unroll
                for (int q = 0; q < 16; q++)
                    acc[q] += __shfl_xor_sync(0xffffffffu, acc[q], off);
            }
            if (lane == 0) {
                float4* dst = (float4*)(g_agg + bv * 16);
                dst[0] = make_float4(acc[0],  acc[1],  acc[2],  acc[3]);
                dst[1] = make_float4(acc[4],  acc[5],  acc[6],  acc[7]);
                dst[2] = make_float4(acc[8],  acc[9],  acc[10], acc[11]);
                dst[3] = make_float4(acc[12], acc[13], acc[14], acc[15]);
            }
        }
    } else if (bx < 3072) {
        // ---- nr block: one batch, 64 rows x 128 outs (R13 body) ----
        int b = bx / 3;
        float* s_Wr = buf;           // 8192 : W_r rows 64..127
        float* s_nd = buf + 8192;    // 4096 : nodes[b]
        for (int i4 = tid; i4 < 2048; i4 += 256)
            *(float4*)&s_Wr[i4 * 4] = *(const float4*)&W_r[8192 + i4 * 4];
        for (int i4 = tid; i4 < 1024; i4 += 256)
            *(float4*)&s_nd[i4 * 4] = *(const float4*)&nodes[(long)b * 4096 + i4 * 4];
        __syncthreads();

        const int rx = tid & 31, ry = tid >> 5;
        const int o0 = rx * 4, v0r = ry * 8;
        u64 acc[8][2];
        {
            ulonglong2 br = *(const ulonglong2*)&b_r[o0];
            #pragma unroll
            for (int vv = 0; vv < 8; vv++) { acc[vv][0] = br.x; acc[vv][1] = br.y; }
        }
        #pragma unroll 2
        for (int k = 0; k < 64; k++) {
            ulonglong2 q = *(const ulonglong2*)&s_Wr[k * 128 + o0];
            #pragma unroll
            for (int vv = 0; vv < 8; vv++) {
                float nv = s_nd[(v0r + vv) * 64 + k];
                u64 np = pk2(nv, nv);
                fma2(acc[vv][0], np, q.x); fma2(acc[vv][1], np, q.y);
            }
        }
        #pragma unroll
        for (int vv = 0; vv < 8; vv++) {
            ulonglong2 o; o.x = acc[vv][0]; o.y = acc[vv][1];
            *(ulonglong2*)&g_nr[(long)(b * 64 + v0r + vv) * 128 + o0] = o;
        }
    } else {
        // ---- fold blocks ----
        float* s_Wu = buf;
        float* s_A  = buf + 8192;
        for (int i = tid; i < 8192; i += 256) s_Wu[i] = W_u[4096 + i];

        if (bx < 3080) {
            int r0 = (bx - 3072) * 8;
            for (int i = tid; i < 1024; i += 256) s_A[i] = W_n[r0 * 128 + i];
            __syncthreads();
            int g = tid & 63, r = tid >> 6;
            for (int rr = r; rr < 8; rr += 4) {
                float acc = 0.f;
                #pragma unroll 8
                for (int m = 0; m < 128; m++)
                    acc += s_A[rr * 128 + m] * s_Wu[m * 64 + g];
                g_Wnb[(r0 + rr) * 64 + g] = acc;
            }
        } else {
            if (tid == 0) g_ctr = 0u;
            for (int i = tid; i < 2048; i += 256) s_A[i] = W_e[i];
            __syncthreads();
            int g = tid & 63, r = tid >> 6;
            for (int rr = r; rr < 16; rr += 4) {
                float acc = 0.f;
                #pragma unroll 8
                for (int m = 0; m < 128; m++)
                    acc += s_A[rr * 128 + m] * s_Wu[m * 64 + g];
                g_Weu[rr * 64 + g] = acc;
            }
            if (tid < 64) {
                float acc = b_u[tid];
                #pragma unroll 8
                for (int m = 0; m < 128; m++)
                    acc += b_m[m] * s_Wu[m * 64 + tid];
                g_cu[tid] = acc;
            }
        }
    }
}

// ---------------------------------------------------------------------------
// k_mpnn: IDENTICAL to R12/R13 (measured 187.9-189.1us, rel_err 5.6e-7).
// ---------------------------------------------------------------------------
#define SMEM_BYTES (25408 * 4)

__global__ void __launch_bounds__(256, 2)
k_mpnn(const int* __restrict__ adj, const float* __restrict__ nodes,
       const float* __restrict__ W_u, const float* __restrict__ W_r,
       float* __restrict__ out)
{
    extern __shared__ float sm[];
    float* s_hT   = sm;
    float* s_W    = sm + 4352;
    float* s_aT   = sm + 12544;
    float* s_T    = sm + 16896;
    float* s_et   = sm + 20992;
    float* s_mask = sm + 25344;
    float* s_red  = s_W;
    __shared__ unsigned s_b;

    int tid = threadIdx.x;
    const int tx = tid & 15, ty = tid >> 4;
    const int g0 = tx * 4,   v0 = ty * 4;
    const int rx = tid & 31, ry = tid >> 5;
    const int o0 = rx * 4,   v0r = ry * 8;

    while (true) {
        if (tid == 0) s_b = atomicAdd(&g_ctr, 1u);
        __syncthreads();
        unsigned b = s_b;
        if (b >= 1024u) break;

        const float* nb = nodes + b * 4096;
        const int*   ab = adj   + b * 4096;
        for (int i4 = tid; i4 < 1024; i4 += 256) {
            int v = i4 >> 4, f = (i4 & 15) * 4;
            float4 hv = *(const float4*)&nb[v * 64 + f];
            s_hT[(f + 0) * 68 + v] = hv.x;
            s_hT[(f + 1) * 68 + v] = hv.y;
            s_hT[(f + 2) * 68 + v] = hv.z;
            s_hT[(f + 3) * 68 + v] = hv.w;
            int4 a4 = *(const int4*)&ab[v * 64 + f];
            s_aT[(f + 0) * 68 + v] = (float)a4.x;
            s_aT[(f + 1) * 68 + v] = (float)a4.y;
            s_aT[(f + 2) * 68 + v] = (float)a4.z;
            s_aT[(f + 3) * 68 + v] = (float)a4.w;
        }
        for (int i4 = tid; i4 < 2048; i4 += 256) {
            int f = i4 >> 5, gq = (i4 & 31) * 4;
            *(float4*)&s_W[f * 128 + gq] = (gq < 64)
                ? *(const float4*)&W_u[f * 64 + gq]
                : *(const float4*)&g_Wnb[f * 64 + gq - 64];
        }
        for (int i = tid; i < 1024; i += 256) {
            s_T[i]        = g_agg[(long)b * 1024 + i];
            s_T[1024 + i] = g_Weu[i];
        }
        if (tid < 64) s_T[2048 + tid] = g_cu[tid];
        __syncthreads();

        if (tid < 64) {
            float s = 0.f;
            #pragma unroll 8
            for (int u = 0; u < 64; u++) s += s_aT[u * 68 + tid];
            s_mask[tid] = (s > 0.f) ? 1.f : 0.f;
        }
        {
            float4 cu4 = *(const float4*)&s_T[2048 + g0];
            #pragma unroll
            for (int i = 0; i < 4; i++) {
                float e0 = cu4.x, e1 = cu4.y, e2 = cu4.z, e3 = cu4.w;
                #pragma unroll
                for (int e = 0; e < 16; e++) {
                    float a = s_T[(v0 + i) * 16 + e];
                    float4 u4 = *(const float4*)&s_T[1024 + e * 64 + g0];
                    e0 += a * u4.x; e1 += a * u4.y; e2 += a * u4.z; e3 += a * u4.w;
                }
                *(float4*)&s_et[(v0 + i) * 64 + g0] = make_float4(e0, e1, e2, e3);
            }
        }
        __syncthreads();
        float mk[4];
        #pragma unroll
        for (int i = 0; i < 4; i++) mk[i] = s_mask[v0 + i];

        for (int pass = 0; pass < 4; pass++) {
            u64 G[4][2], T[4][2];
            #pragma unroll
            for (int i = 0; i < 4; i++) {
                G[i][0] = 0ull; G[i][1] = 0ull;
                T[i][0] = 0ull; T[i][1] = 0ull;
            }
            #pragma unroll 4
            for (int f = 0; f < 64; f++) {
                ulonglong2 wg = *(const ulonglong2*)&s_W[f * 128 + g0];
                ulonglong2 wt = *(const ulonglong2*)&s_W[f * 128 + 64 + g0];
                float4 hv = *(const float4*)&s_hT[f * 68 + v0];
                u64 hp;
                hp = pk2(hv.x, hv.x);
                fma2(G[0][0], hp, wg.x); fma2(G[0][1], hp, wg.y);
                fma2(T[0][0], hp, wt.x); fma2(T[0][1], hp, wt.y);
                hp = pk2(hv.y, hv.y);
                fma2(G[1][0], hp, wg.x); fma2(G[1][1], hp, wg.y);
                fma2(T[1][0], hp, wt.x); fma2(T[1][1], hp, wt.y);
                hp = pk2(hv.z, hv.z);
                fma2(G[2][0], hp, wg.x); fma2(G[2][1], hp, wg.y);
                fma2(T[2][0], hp, wt.x); fma2(T[2][1], hp, wt.y);
                hp = pk2(hv.w, hv.w);
                fma2(G[3][0], hp, wg.x); fma2(G[3][1], hp, wg.y);
                fma2(T[3][0], hp, wt.x); fma2(T[3][1], hp, wt.y);
            }
            #pragma unroll
            for (int i = 0; i < 4; i++) {
                ulonglong2 tv; tv.x = T[i][0]; tv.y = T[i][1];
                *(ulonglong2*)&s_T[(v0 + i) * 64 + g0] = tv;
            }
            __syncthreads();

            u64 S[4][2];
            #pragma unroll
            for (int i = 0; i < 4; i++) { S[i][0] = 0ull; S[i][1] = 0ull; }
            #pragma unroll 4
            for (int u = 0; u < 64; u++) {
                ulonglong2 tp = *(const ulonglong2*)&s_T[u * 64 + g0];
                float4 av = *(const float4*)&s_aT[u * 68 + v0];
                u64 a;
                a = pk2(av.x, av.x); fma2(S[0][0], a, tp.x); fma2(S[0][1], a, tp.y);
                a = pk2(av.y, av.y); fma2(S[1][0], a, tp.x); fma2(S[1][1], a, tp.y);
                a = pk2(av.z, av.z); fma2(S[2][0], a, tp.x); fma2(S[2][1], a, tp.y);
                a = pk2(av.w, av.w); fma2(S[3][0], a, tp.x); fma2(S[3][1], a, tp.y);
            }
            float x[4][4];
            #pragma unroll
            for (int i = 0; i < 4; i++) {
                ulonglong2 e = *(const ulonglong2*)&s_et[(v0 + i) * 64 + g0];
                add2(G[i][0], S[i][0]); add2(G[i][1], S[i][1]);
                add2(G[i][0], e.x);     add2(G[i][1], e.y);
                up2(G[i][0], x[i][0], x[i][1]);
                up2(G[i][1], x[i][2], x[i][3]);
                x[i][0] = fmaxf(x[i][0], 0.f); x[i][1] = fmaxf(x[i][1], 0.f);
                x[i][2] = fmaxf(x[i][2], 0.f); x[i][3] = fmaxf(x[i][3], 0.f);
            }
            #pragma unroll
            for (int j = 0; j < 4; j++) {
                float4 old = *(const float4*)&s_hT[(g0 + j) * 68 + v0];
                float4 nv;
                nv.x = (mk[0] != 0.f) ? x[0][j] : old.x;
                nv.y = (mk[1] != 0.f) ? x[1][j] : old.y;
                nv.z = (mk[2] != 0.f) ? x[2][j] : old.z;
                nv.w = (mk[3] != 0.f) ? x[3][j] : old.w;
                *(float4*)&s_hT[(g0 + j) * 68 + v0] = nv;
            }
            __syncthreads();
        }

        for (int i4 = tid; i4 < 2048; i4 += 256)
            *(float4*)&s_W[i4 * 4] = *(const float4*)&W_r[i4 * 4];
        __syncthreads();

        u64 acc[8][2];
        #pragma unroll
        for (int vv = 0; vv < 8; vv++) {
            float4 f = __ldcg((const float4*)&g_nr[(long)(b * 64 + v0r + vv) * 128 + o0]);
            acc[vv][0] = pk2(f.x, f.y);
            acc[vv][1] = pk2(f.z, f.w);
        }
        #pragma unroll 2
        for (int k = 0; k < 64; k++) {
            ulonglong2 q = *(const ulonglong2*)&s_W[k * 128 + o0];
            float4 h0 = *(const float4*)&s_hT[k * 68 + v0r];
            float4 h1 = *(const float4*)&s_hT[k * 68 + v0r + 4];
            u64 hp;
            hp = pk2(h0.x, h0.x); fma2(acc[0][0], hp, q.x); fma2(acc[0][1], hp, q.y);
            hp = pk2(h0.y, h0.y); fma2(acc[1][0], hp, q.x); fma2(acc[1][1], hp, q.y);
            hp = pk2(h0.z, h0.z); fma2(acc[2][0], hp, q.x); fma2(acc[2][1], hp, q.y);
            hp = pk2(h0.w, h0.w); fma2(acc[3][0], hp, q.x); fma2(acc[3][1], hp, q.y);
            hp = pk2(h1.x, h1.x); fma2(acc[4][0], hp, q.x); fma2(acc[4][1], hp, q.y);
            hp = pk2(h1.y, h1.y); fma2(acc[5][0], hp, q.x); fma2(acc[5][1], hp, q.y);
            hp = pk2(h1.z, h1.z); fma2(acc[6][0], hp, q.x); fma2(acc[6][1], hp, q.y);
            hp = pk2(h1.w, h1.w); fma2(acc[7][0], hp, q.x); fma2(acc[7][1], hp, q.y);
        }
        float oa[4] = {0.f, 0.f, 0.f, 0.f};
        #pragma unroll
        for (int vv = 0; vv < 8; vv++) {
            if (s_mask[v0r + vv] != 0.f) {
                float y0, y1, y2, y3;
                up2(acc[vv][0], y0, y1); up2(acc[vv][1], y2, y3);
                oa[0] += fmaxf(y0, 0.f); oa[1] += fmaxf(y1, 0.f);
                oa[2] += fmaxf(y2, 0.f); oa[3] += fmaxf(y3, 0.f);
            }
        }
        __syncthreads();
        *(float4*)&s_red[ry * 128 + o0] = make_float4(oa[0], oa[1], oa[2], oa[3]);
        __syncthreads();
        if (tid < 128) {
            float s = 0.f;
            #pragma unroll
            for (int t = 0; t < 8; t++) s += s_red[t * 128 + tid];
            out[b * 128 + tid] = s;
        }
        __syncthreads();
    }
}

// ---------------------------------------------------------------------------
// Launch
// ---------------------------------------------------------------------------
extern "C" void kernel_launch(void* const* d_in, const int* in_sizes, int n_in,
                              void* d_out, int out_size)
{
    const int*   adj   = (const int*)  d_in[0];
    const float* nodes = (const float*)d_in[1];
    const float* edges = (const float*)d_in[2];
    const float* W_n   = (const float*)d_in[3];
    const float* W_e   = (const float*)d_in[4];
    const float* b_m   = (const float*)d_in[5];
    const float* W_u   = (const float*)d_in[6];
    const float* b_u   = (const float*)d_in[7];
    const float* W_r   = (const float*)d_in[8];
    const float* b_r   = (const float*)d_in[9];
    float* out = (float*)d_out;

    cudaFuncSetAttribute(k_mpnn, cudaFuncAttributeMaxDynamicSharedMemorySize,
                         SMEM_BYTES);

    k_pre<<<3081, 256>>>(adj, edges, nodes, W_n, W_e, b_m, W_u, b_u, W_r, b_r);
    k_mpnn<<<296, 256, SMEM_BYTES>>>(adj, nodes, W_u, W_r, out);
}